// round 4
// baseline (speedup 1.0000x reference)
#include <cuda_runtime.h>

#define NN 100000
#define EE 1600000

// ---------------- scratch (__device__ globals: no allocation allowed) ----------------
__device__ int   g_src[EE];
__device__ int   g_dst[EE];
__device__ int   g_csr[EE];
__device__ int   g_degi[NN];       // degree incl. self loop
__device__ int   g_rowstart[NN];   // CSR row offsets
__device__ int   g_cursor[NN];
__device__ int   g_blocksum[128];
__device__ float g_dinv[NN];
__device__ float g_G[(size_t)NN * 128];  // pre-scaled features dinv[i]*(X@W)[i]
__device__ float g_H[(size_t)NN * 128];  // layer-1 output

// ---------------- degree / edge preprocessing ----------------
__global__ void k_init(int n) {
    int i = blockIdx.x * blockDim.x + threadIdx.x;
    if (i < n) g_degi[i] = 1;  // self loop
}

// edge_index is int32 (JAX x64-disabled downgrades the requested int64).
__global__ void k_convert_count(const int* __restrict__ ei, int E, int N) {
    int i = blockIdx.x * blockDim.x + threadIdx.x;
    if (i < E) {
        int s = ei[i];
        int d = ei[E + i];
        s = min(max(s, 0), N - 1);   // free safety: no-op for valid data
        d = min(max(d, 0), N - 1);
        g_src[i] = s;
        g_dst[i] = d;
        atomicAdd(&g_degi[d], 1);
    }
}

__global__ void k_dinv(int n) {
    int i = blockIdx.x * blockDim.x + threadIdx.x;
    if (i < n) g_dinv[i] = rsqrtf((float)g_degi[i]);
}

// exclusive scan over (degi-1): per-block Hillis-Steele (1024 elems/block)
__global__ void k_scan1(int n) {
    __shared__ int sh[1024];
    int t = threadIdx.x;
    int i = blockIdx.x * 1024 + t;
    int v = (i < n) ? (g_degi[i] - 1) : 0;
    sh[t] = v;
    __syncthreads();
    for (int off = 1; off < 1024; off <<= 1) {
        int u = (t >= off) ? sh[t - off] : 0;
        __syncthreads();
        sh[t] += u;
        __syncthreads();
    }
    if (i < n) g_rowstart[i] = sh[t] - v;   // exclusive within block
    if (t == 1023) g_blocksum[blockIdx.x] = sh[1023];
}

__global__ void k_scan2(int nb) {  // single block, 128 threads (nb <= 128)
    __shared__ int sh[128];
    int t = threadIdx.x;
    int v = (t < nb) ? g_blocksum[t] : 0;
    sh[t] = v;
    __syncthreads();
    for (int off = 1; off < 128; off <<= 1) {
        int u = (t >= off) ? sh[t - off] : 0;
        __syncthreads();
        sh[t] += u;
        __syncthreads();
    }
    if (t < nb) g_blocksum[t] = sh[t] - v;  // exclusive
}

__global__ void k_scan3(int n) {
    int i = blockIdx.x * blockDim.x + threadIdx.x;
    if (i < n) {
        int r = g_rowstart[i] + g_blocksum[i >> 10];
        g_rowstart[i] = r;
        g_cursor[i] = r;
    }
}

__global__ void k_bin(int E) {
    int i = blockIdx.x * blockDim.x + threadIdx.x;
    if (i < E) {
        int d = g_dst[i];
        int p = atomicAdd(&g_cursor[d], 1);
        g_csr[p] = g_src[i];
    }
}

// ---------------- GEMM with row scale: C[r,c] = dinv[r] * sum_k X[r,k]*W[k,c] ----------------
// 64x64 block tile, 256 threads, 4x4 register tile, BK=16.
// IN_H: X comes from g_H (device-resolved global); output always goes to g_G.
template <bool IN_H>
__global__ void k_gemm_scale(const float* __restrict__ Xp, const float* __restrict__ W,
                             int N, int K, int M) {
    const float* X = IN_H ? (const float*)g_H : Xp;
    float* C = g_G;
    __shared__ float sX[16][65];
    __shared__ float sW[16][64];
    int tid = threadIdx.x;
    int tx = tid & 15;
    int ty = tid >> 4;
    int row0 = blockIdx.x * 64;
    int col0 = blockIdx.y * 64;

    float acc[4][4];
#pragma unroll
    for (int r = 0; r < 4; r++)
#pragma unroll
        for (int c = 0; c < 4; c++) acc[r][c] = 0.f;

    for (int k0 = 0; k0 < K; k0 += 16) {
        {
            int r  = tid >> 2;
            int kk = (tid & 3) * 4;
            int row = row0 + r;
            float4 v = make_float4(0.f, 0.f, 0.f, 0.f);
            if (row < N) v = *reinterpret_cast<const float4*>(&X[(size_t)row * K + k0 + kk]);
            sX[kk + 0][r] = v.x;
            sX[kk + 1][r] = v.y;
            sX[kk + 2][r] = v.z;
            sX[kk + 3][r] = v.w;
        }
        {
            int k  = tid >> 4;
            int c4 = (tid & 15) * 4;
            *reinterpret_cast<float4*>(&sW[k][c4]) =
                *reinterpret_cast<const float4*>(&W[(size_t)(k0 + k) * M + col0 + c4]);
        }
        __syncthreads();
#pragma unroll
        for (int k = 0; k < 16; k++) {
            float a0 = sX[k][ty * 4 + 0];
            float a1 = sX[k][ty * 4 + 1];
            float a2 = sX[k][ty * 4 + 2];
            float a3 = sX[k][ty * 4 + 3];
            float4 b = *reinterpret_cast<const float4*>(&sW[k][tx * 4]);
            acc[0][0] += a0 * b.x; acc[0][1] += a0 * b.y; acc[0][2] += a0 * b.z; acc[0][3] += a0 * b.w;
            acc[1][0] += a1 * b.x; acc[1][1] += a1 * b.y; acc[1][2] += a1 * b.z; acc[1][3] += a1 * b.w;
            acc[2][0] += a2 * b.x; acc[2][1] += a2 * b.y; acc[2][2] += a2 * b.z; acc[2][3] += a2 * b.w;
            acc[3][0] += a3 * b.x; acc[3][1] += a3 * b.y; acc[3][2] += a3 * b.z; acc[3][3] += a3 * b.w;
        }
        __syncthreads();
    }
#pragma unroll
    for (int r = 0; r < 4; r++) {
        int row = row0 + ty * 4 + r;
        if (row < N) {
            float d = g_dinv[row];
#pragma unroll
            for (int c = 0; c < 4; c++)
                C[(size_t)row * M + col0 + tx * 4 + c] = d * acc[r][c];
        }
    }
}

// ---------------- aggregation: warp per node, pull-based ----------------
__global__ void k_agg128(const float* __restrict__ bias, int N) {
    int w = (blockIdx.x * blockDim.x + threadIdx.x) >> 5;
    int lane = threadIdx.x & 31;
    if (w >= N) return;
    int node = w;
    int start = g_rowstart[node];
    int cnt = g_degi[node] - 1;
    const float4* Gv = reinterpret_cast<const float4*>(g_G);
    float4 a = Gv[(size_t)node * 32 + lane];  // self loop
    for (int e = 0; e < cnt; e++) {
        int s = g_csr[start + e];
        float4 gv = Gv[(size_t)s * 32 + lane];
        a.x += gv.x; a.y += gv.y; a.z += gv.z; a.w += gv.w;
    }
    float d = g_dinv[node];
    float4 bq = *reinterpret_cast<const float4*>(&bias[lane * 4]);
    float4 o;
    o.x = fmaxf(d * a.x + bq.x, 0.f);
    o.y = fmaxf(d * a.y + bq.y, 0.f);
    o.z = fmaxf(d * a.z + bq.z, 0.f);
    o.w = fmaxf(d * a.w + bq.w, 0.f);
    reinterpret_cast<float4*>(g_H)[(size_t)node * 32 + lane] = o;
}

__global__ void k_agg64_head(const float* __restrict__ bias,
                             const float* __restrict__ Wd, const float* __restrict__ bd,
                             const float* __restrict__ Wp, const float* __restrict__ bp,
                             float* __restrict__ out, int N) {
    int w = (blockIdx.x * blockDim.x + threadIdx.x) >> 5;
    int lane = threadIdx.x & 31;
    if (w >= N) return;
    int node = w;
    int start = g_rowstart[node];
    int cnt = g_degi[node] - 1;
    const float2* Gv = reinterpret_cast<const float2*>(g_G);
    float2 a = Gv[(size_t)node * 32 + lane];
    for (int e = 0; e < cnt; e++) {
        int s = g_csr[start + e];
        float2 gv = Gv[(size_t)s * 32 + lane];
        a.x += gv.x; a.y += gv.y;
    }
    float d = g_dinv[node];
    float h0 = fmaxf(d * a.x + bias[lane * 2 + 0], 0.f);
    float h1 = fmaxf(d * a.y + bias[lane * 2 + 1], 0.f);
    float dd = h0 * Wd[lane * 2 + 0] + h1 * Wd[lane * 2 + 1];
    float pp = h0 * Wp[lane * 2 + 0] + h1 * Wp[lane * 2 + 1];
#pragma unroll
    for (int off = 16; off > 0; off >>= 1) {
        dd += __shfl_xor_sync(0xFFFFFFFFu, dd, off);
        pp += __shfl_xor_sync(0xFFFFFFFFu, pp, off);
    }
    if (lane == 0) {
        out[node]     = dd + bd[0];
        out[N + node] = pp + bp[0];
    }
}

// ---------------- launch ----------------
extern "C" void kernel_launch(void* const* d_in, const int* in_sizes, int n_in,
                              void* d_out, int out_size) {
    const float* x  = (const float*)d_in[0];
    const int*   ei = (const int*)d_in[1];   // int32 edge_index (JAX x64 off)
    const float* W1 = (const float*)d_in[2];
    const float* b1 = (const float*)d_in[3];
    const float* W2 = (const float*)d_in[4];
    const float* b2 = (const float*)d_in[5];
    const float* Wd = (const float*)d_in[6];
    const float* bd = (const float*)d_in[7];
    const float* Wp = (const float*)d_in[8];
    const float* bp = (const float*)d_in[9];
    float* out = (float*)d_out;

    const int N = in_sizes[0] / 64;       // 100000
    const int E = in_sizes[1] / 2;        // 1600000

    const int T = 256;
    int gN = (N + T - 1) / T;
    int gE = (E + T - 1) / T;
    int nScanBlocks = (N + 1023) / 1024;  // 98

    // preprocessing: degrees, dinv, CSR by destination
    k_init<<<gN, T>>>(N);
    k_convert_count<<<gE, T>>>(ei, E, N);
    k_dinv<<<gN, T>>>(N);
    k_scan1<<<nScanBlocks, 1024>>>(N);
    k_scan2<<<1, 128>>>(nScanBlocks);
    k_scan3<<<gN, T>>>(N);
    k_bin<<<gE, T>>>(E);

    // layer 1: g = dinv*(x@W1) ; H = relu(dinv*agg(g) + b1)
    {
        dim3 grid((N + 63) / 64, 128 / 64);
        k_gemm_scale<false><<<grid, 256>>>(x, W1, N, 64, 128);
    }
    {
        int blocks = (N + 7) / 8;  // 8 warps per 256-thread block
        k_agg128<<<blocks, 256>>>(b1, N);
    }

    // layer 2: g = dinv*(H@W2) ; fused agg + relu + dual heads
    {
        dim3 grid((N + 63) / 64, 64 / 64);
        k_gemm_scale<true><<<grid, 256>>>(nullptr, W2, N, 128, 64);
    }
    {
        int blocks = (N + 7) / 8;
        k_agg64_head<<<blocks, 256>>>(b2, Wd, bd, Wp, bp, out, N);
    }
}

// round 5
// speedup vs baseline: 1.1304x; 1.1304x over previous
#include <cuda_runtime.h>
#include <cuda_fp16.h>
#include <mma.h>

using namespace nvcuda;

#define NN 100000
#define NPAD 100032   // 1563 * 64 (row padding so wmma tile loads never fault)
#define EE 1600000

// ---------------- scratch (__device__ globals zero-initialized; no allocs) ----------------
__device__ int    g_csr[EE];
__device__ int    g_degi[NN];       // degree incl. self loop
__device__ int    g_rowstart[NN];
__device__ int    g_cursor[NN];
__device__ int    g_blocksum[128];
__device__ float  g_dinv[NN];
__device__ __half g_Xh[(size_t)NPAD * 64];    // fp16 copy of x (pad rows stay 0)
__device__ __half g_W1h[64 * 128];
__device__ __half g_W2h[128 * 64];
__device__ __half g_Gh[(size_t)NPAD * 128];   // dinv-scaled features (agg input)
__device__ __half g_Hh[(size_t)NPAD * 128];   // layer-1 output (pad rows stay 0)

// ---------------- preprocessing ----------------
__global__ void k_init(int n) {
    int i = blockIdx.x * blockDim.x + threadIdx.x;
    if (i < n) g_degi[i] = 1;  // self loop
}

// edge_index is int32 (JAX x64-disabled downgrades the requested int64)
__global__ void k_count(const int* __restrict__ ei, int E, int N) {
    int i = blockIdx.x * blockDim.x + threadIdx.x;
    if (i < E) {
        int d = min(max(ei[E + i], 0), N - 1);
        atomicAdd(&g_degi[d], 1);
    }
}

__global__ void k_dinv(int n) {
    int i = blockIdx.x * blockDim.x + threadIdx.x;
    if (i < n) g_dinv[i] = rsqrtf((float)g_degi[i]);
}

// exclusive scan over (degi-1)
__global__ void k_scan1(int n) {
    __shared__ int sh[1024];
    int t = threadIdx.x;
    int i = blockIdx.x * 1024 + t;
    int v = (i < n) ? (g_degi[i] - 1) : 0;
    sh[t] = v;
    __syncthreads();
    for (int off = 1; off < 1024; off <<= 1) {
        int u = (t >= off) ? sh[t - off] : 0;
        __syncthreads();
        sh[t] += u;
        __syncthreads();
    }
    if (i < n) g_rowstart[i] = sh[t] - v;
    if (t == 1023) g_blocksum[blockIdx.x] = sh[1023];
}

__global__ void k_scan2(int nb) {
    __shared__ int sh[128];
    int t = threadIdx.x;
    int v = (t < nb) ? g_blocksum[t] : 0;
    sh[t] = v;
    __syncthreads();
    for (int off = 1; off < 128; off <<= 1) {
        int u = (t >= off) ? sh[t - off] : 0;
        __syncthreads();
        sh[t] += u;
        __syncthreads();
    }
    if (t < nb) g_blocksum[t] = sh[t] - v;
}

__global__ void k_scan3(int n) {
    int i = blockIdx.x * blockDim.x + threadIdx.x;
    if (i < n) {
        int r = g_rowstart[i] + g_blocksum[i >> 10];
        g_rowstart[i] = r;
        g_cursor[i] = r;
    }
}

__global__ void k_bin(const int* __restrict__ ei, int E, int N) {
    int i = blockIdx.x * blockDim.x + threadIdx.x;
    if (i < E) {
        int s = min(max(ei[i], 0), N - 1);
        int d = min(max(ei[E + i], 0), N - 1);
        int p = atomicAdd(&g_cursor[d], 1);
        g_csr[p] = s;
    }
}

// ---------------- fp16 conversion ----------------
__global__ void k_convert_x(const float* __restrict__ x, int quads) {
    int i = blockIdx.x * blockDim.x + threadIdx.x;
    if (i < quads) {
        float4 v = reinterpret_cast<const float4*>(x)[i];
        __half2 a = __floats2half2_rn(v.x, v.y);
        __half2 b = __floats2half2_rn(v.z, v.w);
        uint2 u;
        u.x = *reinterpret_cast<unsigned*>(&a);
        u.y = *reinterpret_cast<unsigned*>(&b);
        reinterpret_cast<uint2*>(g_Xh)[i] = u;
    }
}

__global__ void k_convert_w(const float* __restrict__ W1, const float* __restrict__ W2) {
    int i = blockIdx.x * blockDim.x + threadIdx.x;
    if (i < 64 * 128) g_W1h[i] = __float2half_rn(W1[i]);
    if (i < 128 * 64) g_W2h[i] = __float2half_rn(W2[i]);
}

// ---------------- tensor-core GEMM: Gh[r,c] = fp16( dinv[r] * sum_k A[r,k]*W[k,c] ) ----------------
// Block: 256 threads = 8 warps (4 in M-rows x 2 in N-cols), block tile 64 x M.
template <int K, int M>
__global__ void k_gemm_wmma(int N) {
    constexpr int NF = M / 32;              // wmma n-frags per warp (each warp: 16 x M/2)
    const __half* A = (K == 64) ? g_Xh : g_Hh;
    const __half* W = (K == 64) ? g_W1h : g_W2h;

    __shared__ float sc[8][16][68];

    int wid = threadIdx.x >> 5;
    int lane = threadIdx.x & 31;
    int wm = wid & 3;
    int wn = wid >> 2;
    int row0 = blockIdx.x * 64 + wm * 16;
    int col0 = wn * (M / 2);

    wmma::fragment<wmma::accumulator, 16, 16, 16, float> acc[NF];
#pragma unroll
    for (int f = 0; f < NF; f++) wmma::fill_fragment(acc[f], 0.f);

    for (int k0 = 0; k0 < K; k0 += 16) {
        wmma::fragment<wmma::matrix_a, 16, 16, 16, __half, wmma::row_major> a;
        wmma::load_matrix_sync(a, A + (size_t)row0 * K + k0, K);
#pragma unroll
        for (int f = 0; f < NF; f++) {
            wmma::fragment<wmma::matrix_b, 16, 16, 16, __half, wmma::row_major> b;
            wmma::load_matrix_sync(b, W + (size_t)k0 * M + col0 + f * 16, M);
            wmma::mma_sync(acc[f], a, b, acc[f]);
        }
    }
#pragma unroll
    for (int f = 0; f < NF; f++)
        wmma::store_matrix_sync(&sc[wid][0][f * 16], acc[f], 68, wmma::mem_row_major);
    __syncwarp();

    for (int idx = lane; idx < 16 * (M / 2); idx += 32) {
        int r = idx / (M / 2);
        int c = idx % (M / 2);
        int row = row0 + r;
        if (row < N) {
            float v = sc[wid][r][c] * g_dinv[row];
            g_Gh[(size_t)row * M + col0 + c] = __float2half_rn(v);
        }
    }
}

// ---------------- aggregation: warp per node, pull-based, fp16 gather / fp32 accum ----------------
__device__ __forceinline__ float4 unpack4(uint2 u) {
    __half2 h0 = *reinterpret_cast<__half2*>(&u.x);
    __half2 h1 = *reinterpret_cast<__half2*>(&u.y);
    float2 f0 = __half22float2(h0);
    float2 f1 = __half22float2(h1);
    return make_float4(f0.x, f0.y, f1.x, f1.y);
}

__global__ void k_agg128(const float* __restrict__ bias, int N) {
    int w = (blockIdx.x * blockDim.x + threadIdx.x) >> 5;
    int lane = threadIdx.x & 31;
    if (w >= N) return;
    int start = g_rowstart[w];
    int cnt = g_degi[w] - 1;
    const uint2* G = reinterpret_cast<const uint2*>(g_Gh);  // 4 halves/lane, 32 lanes = 128
    float4 a = unpack4(G[(size_t)w * 32 + lane]);           // self loop
    for (int e = 0; e < cnt; e++) {
        int s = g_csr[start + e];
        float4 v = unpack4(G[(size_t)s * 32 + lane]);
        a.x += v.x; a.y += v.y; a.z += v.z; a.w += v.w;
    }
    float d = g_dinv[w];
    float4 bq = *reinterpret_cast<const float4*>(&bias[lane * 4]);
    __half2 o0 = __floats2half2_rn(fmaxf(d * a.x + bq.x, 0.f), fmaxf(d * a.y + bq.y, 0.f));
    __half2 o1 = __floats2half2_rn(fmaxf(d * a.z + bq.z, 0.f), fmaxf(d * a.w + bq.w, 0.f));
    uint2 u;
    u.x = *reinterpret_cast<unsigned*>(&o0);
    u.y = *reinterpret_cast<unsigned*>(&o1);
    reinterpret_cast<uint2*>(g_Hh)[(size_t)w * 32 + lane] = u;
}

__global__ void k_agg64_head(const float* __restrict__ bias,
                             const float* __restrict__ Wd, const float* __restrict__ bd,
                             const float* __restrict__ Wp, const float* __restrict__ bp,
                             float* __restrict__ out, int N) {
    int w = (blockIdx.x * blockDim.x + threadIdx.x) >> 5;
    int lane = threadIdx.x & 31;
    if (w >= N) return;
    int start = g_rowstart[w];
    int cnt = g_degi[w] - 1;
    const unsigned* G = reinterpret_cast<const unsigned*>(g_Gh);  // 2 halves/lane, 32 lanes = 64
    float2 a;
    {
        unsigned v = G[(size_t)w * 32 + lane];
        a = __half22float2(*reinterpret_cast<__half2*>(&v));
    }
    for (int e = 0; e < cnt; e++) {
        int s = g_csr[start + e];
        unsigned v = G[(size_t)s * 32 + lane];
        float2 f = __half22float2(*reinterpret_cast<__half2*>(&v));
        a.x += f.x; a.y += f.y;
    }
    float d = g_dinv[w];
    float h0 = fmaxf(d * a.x + bias[lane * 2 + 0], 0.f);
    float h1 = fmaxf(d * a.y + bias[lane * 2 + 1], 0.f);
    float dd = h0 * Wd[lane * 2 + 0] + h1 * Wd[lane * 2 + 1];
    float pp = h0 * Wp[lane * 2 + 0] + h1 * Wp[lane * 2 + 1];
#pragma unroll
    for (int off = 16; off > 0; off >>= 1) {
        dd += __shfl_xor_sync(0xFFFFFFFFu, dd, off);
        pp += __shfl_xor_sync(0xFFFFFFFFu, pp, off);
    }
    if (lane == 0) {
        out[w]     = dd + bd[0];
        out[N + w] = pp + bp[0];
    }
}

// ---------------- launch ----------------
extern "C" void kernel_launch(void* const* d_in, const int* in_sizes, int n_in,
                              void* d_out, int out_size) {
    const float* x  = (const float*)d_in[0];
    const int*   ei = (const int*)d_in[1];   // int32 edge_index
    const float* W1 = (const float*)d_in[2];
    const float* b1 = (const float*)d_in[3];
    const float* W2 = (const float*)d_in[4];
    const float* b2 = (const float*)d_in[5];
    const float* Wd = (const float*)d_in[6];
    const float* bd = (const float*)d_in[7];
    const float* Wp = (const float*)d_in[8];
    const float* bp = (const float*)d_in[9];
    float* out = (float*)d_out;

    const int N = in_sizes[0] / 64;   // 100000
    const int E = in_sizes[1] / 2;    // 1600000

    const int T = 256;
    int gN = (N + T - 1) / T;
    int gE = (E + T - 1) / T;
    int nScanBlocks = (N + 1023) / 1024;

    // CSR build
    k_init<<<gN, T>>>(N);
    k_count<<<gE, T>>>(ei, E, N);
    k_dinv<<<gN, T>>>(N);
    k_scan1<<<nScanBlocks, 1024>>>(N);
    k_scan2<<<1, 128>>>(nScanBlocks);
    k_scan3<<<gN, T>>>(N);
    k_bin<<<gE, T>>>(ei, E, N);

    // fp16 conversions
    int quads = N * 64 / 4;
    k_convert_x<<<(quads + T - 1) / T, T>>>(x, quads);
    k_convert_w<<<(128 * 64 + T - 1) / T, T>>>(W1, W2);

    int gemmBlocks = (N + 63) / 64;           // 1563 (NPAD/64)
    int aggBlocks = (N + 7) / 8;              // 8 warps / block

    // layer 1
    k_gemm_wmma<64, 128><<<gemmBlocks, 256>>>(N);
    k_agg128<<<aggBlocks, 256>>>(b1, N);

    // layer 2 + heads
    k_gemm_wmma<128, 64><<<gemmBlocks, 256>>>(N);
    k_agg64_head<<<aggBlocks, 256>>>(b2, Wd, bd, Wp, bp, out, N);
}